// round 4
// baseline (speedup 1.0000x reference)
#include <cuda_runtime.h>
#include <cstdint>

#define MROWS 32768
#define NQ 3
#define NE 256
#define ED 32
#define CBPAD 33

// ---------------- scratch ----------------
__device__ float g_loss;
__device__ float g_h0[(size_t)MROWS * 512];
__device__ float g_h1[(size_t)MROWS * 256];
__device__ float g_h2[(size_t)MROWS * 128];
__device__ float g_lat[(size_t)MROWS * ED];
__device__ float g_xq [(size_t)MROWS * ED];
__device__ float g_g0[(size_t)MROWS * 128];
__device__ float g_g1[(size_t)MROWS * 256];
__device__ float g_g2[(size_t)MROWS * 512];

__device__ __forceinline__ uint32_t tf32_hi_bits(float x) {
    uint32_t u; asm("cvt.rna.tf32.f32 %0, %1;" : "=r"(u) : "f"(x)); return u;
}

__device__ __forceinline__ void mma_tf32(float* c,
    uint32_t a0, uint32_t a1, uint32_t a2, uint32_t a3, uint32_t b0, uint32_t b1) {
    asm volatile(
        "mma.sync.aligned.m16n8k8.row.col.f32.tf32.tf32.f32 "
        "{%0,%1,%2,%3}, {%4,%5,%6,%7}, {%8,%9}, {%0,%1,%2,%3};"
        : "+f"(c[0]), "+f"(c[1]), "+f"(c[2]), "+f"(c[3])
        : "r"(a0), "r"(a1), "r"(a2), "r"(a3), "r"(b0), "r"(b1));
}

// ---------------- HMMA 3xTF32 GEMM: C = relu?(A(MxK) @ W(NxK)^T + bias) ----------------
// CTA tile 128(M) x 64(N) x 32(K). 256 threads, 8 warps (4M x 2N), warp tile 32x32.
// smem layout: k-permuted rows (k -> (k&3)*8 + (k>>2)), pitch 36 words.
#define APITCH 36
#define SM_A_HI 0
#define SM_A_LO (128 * APITCH)
#define SM_B_HI (256 * APITCH)
#define SM_B_LO (320 * APITCH)
#define SM_WORDS (384 * APITCH)

template<bool RELU>
__global__ void __launch_bounds__(256, 2)
gemm_hmma_kernel(const float* __restrict__ A, const float* __restrict__ W,
                 const float* __restrict__ bias, float* __restrict__ C,
                 int N, int K)
{
    extern __shared__ uint32_t sm[];

    const int tid = threadIdx.x;
    const int bn = blockIdx.x * 64;
    const int bm = blockIdx.y * 128;
    const int w = tid >> 5, lane = tid & 31;
    const int wm = (w & 3) * 32;
    const int wn = (w >> 2) * 32;
    const int qr = lane >> 2;
    const int qc = lane & 3;

    float acc[2][4][4];
    #pragma unroll
    for (int i = 0; i < 2; i++)
        #pragma unroll
        for (int j = 0; j < 4; j++)
            #pragma unroll
            for (int k = 0; k < 4; k++) acc[i][j][k] = 0.f;

    const int nk = K >> 5;
    const int k4 = K >> 2;

    // staging decomposition (fixed per thread)
    const int ar_[4] = {(tid + 0) >> 3, (tid + 256) >> 3, (tid + 512) >> 3, (tid + 768) >> 3};
    const int ac4 = tid & 7;   // same for all i since 256 % 8 == 0
    const int br_[2] = {(tid + 0) >> 3, (tid + 256) >> 3};

    float4 pa[4], pb[2];
    {   // prefetch chunk 0
        const float4* Ag = (const float4*)A + (size_t)bm * k4;
        const float4* Wg = (const float4*)W + (size_t)bn * k4;
        #pragma unroll
        for (int i = 0; i < 4; i++) pa[i] = Ag[(size_t)ar_[i] * k4 + ac4];
        #pragma unroll
        for (int i = 0; i < 2; i++) pb[i] = Wg[(size_t)br_[i] * k4 + ac4];
    }

    for (int ck = 0; ck < nk; ck++) {
        __syncthreads();
        // ---- split + store to permuted smem ----
        #pragma unroll
        for (int i = 0; i < 4; i++) {
            const int base = ar_[i] * APITCH + ac4;   // + j*8
            float v[4] = {pa[i].x, pa[i].y, pa[i].z, pa[i].w};
            #pragma unroll
            for (int j = 0; j < 4; j++) {
                uint32_t h = tf32_hi_bits(v[j]);
                sm[SM_A_HI + base + j * 8] = h;
                sm[SM_A_LO + base + j * 8] = tf32_hi_bits(v[j] - __uint_as_float(h));
            }
        }
        #pragma unroll
        for (int i = 0; i < 2; i++) {
            const int base = br_[i] * APITCH + ac4;
            float v[4] = {pb[i].x, pb[i].y, pb[i].z, pb[i].w};
            #pragma unroll
            for (int j = 0; j < 4; j++) {
                uint32_t h = tf32_hi_bits(v[j]);
                sm[SM_B_HI + base + j * 8] = h;
                sm[SM_B_LO + base + j * 8] = tf32_hi_bits(v[j] - __uint_as_float(h));
            }
        }
        __syncthreads();

        // ---- prefetch next chunk (hidden behind MMAs) ----
        if (ck + 1 < nk) {
            const float4* Ag = (const float4*)A + (size_t)bm * k4 + (ck + 1) * 8;
            const float4* Wg = (const float4*)W + (size_t)bn * k4 + (ck + 1) * 8;
            #pragma unroll
            for (int i = 0; i < 4; i++) pa[i] = Ag[(size_t)ar_[i] * k4 + ac4];
            #pragma unroll
            for (int i = 0; i < 2; i++) pb[i] = Wg[(size_t)br_[i] * k4 + ac4];
        }

        // ---- compute ----
        uint32_t a0[2][8], a1[2][8];   // rows qr / qr+8, per mt: t = 0..7 (k = qc + 4t)
        // A hi
        #pragma unroll
        for (int mt = 0; mt < 2; mt++) {
            const int b0 = SM_A_HI + (wm + mt * 16 + qr) * APITCH + qc * 8;
            uint4 v0 = *(const uint4*)&sm[b0];
            uint4 v1 = *(const uint4*)&sm[b0 + 4];
            a0[mt][0]=v0.x; a0[mt][1]=v0.y; a0[mt][2]=v0.z; a0[mt][3]=v0.w;
            a0[mt][4]=v1.x; a0[mt][5]=v1.y; a0[mt][6]=v1.z; a0[mt][7]=v1.w;
            const int b1 = b0 + 8 * APITCH;
            uint4 u0 = *(const uint4*)&sm[b1];
            uint4 u1 = *(const uint4*)&sm[b1 + 4];
            a1[mt][0]=u0.x; a1[mt][1]=u0.y; a1[mt][2]=u0.z; a1[mt][3]=u0.w;
            a1[mt][4]=u1.x; a1[mt][5]=u1.y; a1[mt][6]=u1.z; a1[mt][7]=u1.w;
        }
        // passes 1 (hi*hi) and 2 (hi*lo)
        #pragma unroll
        for (int nt = 0; nt < 4; nt++) {
            const int bb = (wn + nt * 8 + qr) * APITCH + qc * 8;
            uint32_t bh[8];
            {
                uint4 v0 = *(const uint4*)&sm[SM_B_HI + bb];
                uint4 v1 = *(const uint4*)&sm[SM_B_HI + bb + 4];
                bh[0]=v0.x; bh[1]=v0.y; bh[2]=v0.z; bh[3]=v0.w;
                bh[4]=v1.x; bh[5]=v1.y; bh[6]=v1.z; bh[7]=v1.w;
            }
            #pragma unroll
            for (int ks = 0; ks < 4; ks++)
                #pragma unroll
                for (int mt = 0; mt < 2; mt++)
                    mma_tf32(acc[mt][nt], a0[mt][2*ks], a1[mt][2*ks],
                             a0[mt][2*ks+1], a1[mt][2*ks+1], bh[2*ks], bh[2*ks+1]);
            uint32_t bl[8];
            {
                uint4 v0 = *(const uint4*)&sm[SM_B_LO + bb];
                uint4 v1 = *(const uint4*)&sm[SM_B_LO + bb + 4];
                bl[0]=v0.x; bl[1]=v0.y; bl[2]=v0.z; bl[3]=v0.w;
                bl[4]=v1.x; bl[5]=v1.y; bl[6]=v1.z; bl[7]=v1.w;
            }
            #pragma unroll
            for (int ks = 0; ks < 4; ks++)
                #pragma unroll
                for (int mt = 0; mt < 2; mt++)
                    mma_tf32(acc[mt][nt], a0[mt][2*ks], a1[mt][2*ks],
                             a0[mt][2*ks+1], a1[mt][2*ks+1], bl[2*ks], bl[2*ks+1]);
        }
        // pass 3 (lo*hi): reload A as lo
        #pragma unroll
        for (int mt = 0; mt < 2; mt++) {
            const int b0 = SM_A_LO + (wm + mt * 16 + qr) * APITCH + qc * 8;
            uint4 v0 = *(const uint4*)&sm[b0];
            uint4 v1 = *(const uint4*)&sm[b0 + 4];
            a0[mt][0]=v0.x; a0[mt][1]=v0.y; a0[mt][2]=v0.z; a0[mt][3]=v0.w;
            a0[mt][4]=v1.x; a0[mt][5]=v1.y; a0[mt][6]=v1.z; a0[mt][7]=v1.w;
            const int b1 = b0 + 8 * APITCH;
            uint4 u0 = *(const uint4*)&sm[b1];
            uint4 u1 = *(const uint4*)&sm[b1 + 4];
            a1[mt][0]=u0.x; a1[mt][1]=u0.y; a1[mt][2]=u0.z; a1[mt][3]=u0.w;
            a1[mt][4]=u1.x; a1[mt][5]=u1.y; a1[mt][6]=u1.z; a1[mt][7]=u1.w;
        }
        #pragma unroll
        for (int nt = 0; nt < 4; nt++) {
            const int bb = SM_B_HI + (wn + nt * 8 + qr) * APITCH + qc * 8;
            uint32_t bh[8];
            uint4 v0 = *(const uint4*)&sm[bb];
            uint4 v1 = *(const uint4*)&sm[bb + 4];
            bh[0]=v0.x; bh[1]=v0.y; bh[2]=v0.z; bh[3]=v0.w;
            bh[4]=v1.x; bh[5]=v1.y; bh[6]=v1.z; bh[7]=v1.w;
            #pragma unroll
            for (int ks = 0; ks < 4; ks++)
                #pragma unroll
                for (int mt = 0; mt < 2; mt++)
                    mma_tf32(acc[mt][nt], a0[mt][2*ks], a1[mt][2*ks],
                             a0[mt][2*ks+1], a1[mt][2*ks+1], bh[2*ks], bh[2*ks+1]);
        }
    }

    // ---- epilogue: bias + relu, direct float2 stores ----
    #pragma unroll
    for (int nt = 0; nt < 4; nt++) {
        const int col = bn + wn + nt * 8 + qc * 2;
        const float b0 = bias[col], b1 = bias[col + 1];
        #pragma unroll
        for (int mt = 0; mt < 2; mt++) {
            const int row = bm + wm + mt * 16 + qr;
            float2 v0, v1;
            v0.x = acc[mt][nt][0] + b0; v0.y = acc[mt][nt][1] + b1;
            v1.x = acc[mt][nt][2] + b0; v1.y = acc[mt][nt][3] + b1;
            if (RELU) {
                v0.x = fmaxf(v0.x, 0.f); v0.y = fmaxf(v0.y, 0.f);
                v1.x = fmaxf(v1.x, 0.f); v1.y = fmaxf(v1.y, 0.f);
            }
            *(float2*)(C + (size_t)row * N + col) = v0;
            *(float2*)(C + (size_t)(row + 8) * N + col) = v1;
        }
    }
}

// ---------------- SIMT fp32 GEMM (N=32 latent layer) ----------------
template<int BM, int BN, int BK, int TM, int TN, bool RELU>
__global__ void __launch_bounds__((BM/TM)*(BN/TN))
gemm_nt_kernel(const float* __restrict__ A, const float* __restrict__ W,
               const float* __restrict__ bias, float* __restrict__ C,
               int M, int N, int K)
{
    constexpr int THREADS = (BM/TM)*(BN/TN);
    __shared__ float As[BK][BM];
    __shared__ float Ws[BK][BN];

    const int bm = blockIdx.y * BM;
    const int bn = blockIdx.x * BN;
    const int tid = threadIdx.x;
    const int tn = (tid % (BN/TN)) * TN;
    const int tm = (tid / (BN/TN)) * TM;

    float acc[TM][TN];
    #pragma unroll
    for (int i = 0; i < TM; i++)
        #pragma unroll
        for (int j = 0; j < TN; j++) acc[i][j] = 0.f;

    for (int k0 = 0; k0 < K; k0 += BK) {
        constexpr int A_LOADS = (BM*BK) / (4*THREADS);
        #pragma unroll
        for (int i = 0; i < A_LOADS; i++) {
            int idx = (tid + i*THREADS) * 4;
            int r = idx / BK, c = idx % BK;
            float4 v = *(const float4*)(A + (size_t)(bm + r)*K + k0 + c);
            As[c+0][r] = v.x; As[c+1][r] = v.y; As[c+2][r] = v.z; As[c+3][r] = v.w;
        }
        constexpr int W_LOADS = (BN*BK) / (4*THREADS);
        #pragma unroll
        for (int i = 0; i < W_LOADS; i++) {
            int idx = (tid + i*THREADS) * 4;
            int r = idx / BK, c = idx % BK;
            float4 v = *(const float4*)(W + (size_t)(bn + r)*K + k0 + c);
            Ws[c+0][r] = v.x; Ws[c+1][r] = v.y; Ws[c+2][r] = v.z; Ws[c+3][r] = v.w;
        }
        __syncthreads();

        #pragma unroll
        for (int k = 0; k < BK; k++) {
            float ar[TM], wr[TN];
            #pragma unroll
            for (int i = 0; i < TM; i += 4) {
                float4 v = *(const float4*)(&As[k][tm + i]);
                ar[i+0] = v.x; ar[i+1] = v.y; ar[i+2] = v.z; ar[i+3] = v.w;
            }
            #pragma unroll
            for (int j = 0; j < TN; j += 4) {
                float4 v = *(const float4*)(&Ws[k][tn + j]);
                wr[j+0] = v.x; wr[j+1] = v.y; wr[j+2] = v.z; wr[j+3] = v.w;
            }
            #pragma unroll
            for (int i = 0; i < TM; i++)
                #pragma unroll
                for (int j = 0; j < TN; j++)
                    acc[i][j] = fmaf(ar[i], wr[j], acc[i][j]);
        }
        __syncthreads();
    }

    #pragma unroll
    for (int i = 0; i < TM; i++)
        #pragma unroll
        for (int j = 0; j < TN; j++) {
            float v = acc[i][j] + bias[bn + tn + j];
            if (RELU) v = fmaxf(v, 0.f);
            C[(size_t)(bm + tm + i)*N + bn + tn + j] = v;
        }
}

// ---------------- fused residual-VQ kernel ----------------
__global__ void __launch_bounds__(NE)
vq_kernel(const float* __restrict__ latent,
          const float* __restrict__ cb0, const float* __restrict__ cb1,
          const float* __restrict__ cb2,
          float* __restrict__ xq,
          float* __restrict__ out_idx, float* __restrict__ out_oh,
          float* __restrict__ out_logits,
          int rows_per_block)
{
    extern __shared__ float smf[];
    float* cbs   = smf;
    float* cnorm = cbs + NQ*NE*CBPAD;
    float* resid = cnorm + NQ*NE;
    float* xqrow = resid + ED;
    float* red_v = xqrow + ED;
    int*   red_i = (int*)(red_v + NE);
    float* s_rn  = (float*)(red_i + NE);

    const int t = threadIdx.x;

    const float* srcs[NQ] = {cb0, cb1, cb2};
    for (int q = 0; q < NQ; q++)
        for (int i = t; i < NE*ED; i += NE) {
            int r = i / ED, c = i % ED;
            cbs[(q*NE + r)*CBPAD + c] = srcs[q][i];
        }
    __syncthreads();
    for (int q = 0; q < NQ; q++) {
        const float* row = &cbs[(q*NE + t)*CBPAD];
        float s = 0.f;
        #pragma unroll
        for (int k = 0; k < ED; k++) s = fmaf(row[k], row[k], s);
        cnorm[q*NE + t] = s;
    }
    __syncthreads();

    float loss_acc = 0.f;
    const int row0 = blockIdx.x * rows_per_block;
    const int row1 = min(row0 + rows_per_block, MROWS);

    for (int r = row0; r < row1; r++) {
        if (t < ED) { resid[t] = latent[(size_t)r*ED + t]; xqrow[t] = 0.f; }
        __syncthreads();

        for (int q = 0; q < NQ; q++) {
            if (t < 32) {
                float v = resid[t]; v = v*v;
                #pragma unroll
                for (int o = 16; o; o >>= 1) v += __shfl_xor_sync(0xffffffffu, v, o);
                if (t == 0) s_rn[0] = v;
            }
            __syncthreads();
            const float rnorm = s_rn[0];

            const float* crow = &cbs[(q*NE + t)*CBPAD];
            float dot = 0.f;
            #pragma unroll
            for (int k = 0; k < ED; k++) dot = fmaf(resid[k], crow[k], dot);
            float d = rnorm + cnorm[q*NE + t] - 2.f*dot;
            out_logits[((size_t)r*NQ + q)*NE + t] = d;

            red_v[t] = d; red_i[t] = t;
            __syncthreads();
            #pragma unroll
            for (int s = NE/2; s > 0; s >>= 1) {
                if (t < s) {
                    float v2 = red_v[t+s]; int i2 = red_i[t+s];
                    if (v2 < red_v[t] || (v2 == red_v[t] && i2 < red_i[t])) {
                        red_v[t] = v2; red_i[t] = i2;
                    }
                }
                __syncthreads();
            }
            const int best = red_i[0];

            out_oh[((size_t)r*NQ + q)*NE + t] = (t == best) ? 1.f : 0.f;
            if (t == 0) out_idx[(size_t)r*NQ + q] = (float)best;

            if (t < 32) {
                float c  = cbs[(q*NE + best)*CBPAD + t];
                float rv = resid[t];
                float diff = c - rv;
                float xres = rv + diff;
                float sq = diff*diff;
                #pragma unroll
                for (int o = 16; o; o >>= 1) sq += __shfl_xor_sync(0xffffffffu, sq, o);
                if (t == 0) loss_acc += sq;
                resid[t] = rv - xres;
                xqrow[t] += xres;
            }
            __syncthreads();
        }
        if (t < ED) xq[(size_t)r*ED + t] = xqrow[t];
        __syncthreads();
    }
    if (t == 0) atomicAdd(&g_loss, loss_acc);
}

__global__ void zero_loss_kernel() { g_loss = 0.f; }

__global__ void finalize_kernel(float* __restrict__ loss_out)
{
    loss_out[0] = g_loss * (1.25f / (3.0f * (float)MROWS * (float)ED));
}

// ---------------- launch ----------------
extern "C" void kernel_launch(void* const* d_in, const int* in_sizes, int n_in,
                              void* d_out, int out_size)
{
    const float* x   = (const float*)d_in[0];
    const float* ew[4] = {(const float*)d_in[1], (const float*)d_in[3],
                          (const float*)d_in[5], (const float*)d_in[7]};
    const float* eb[4] = {(const float*)d_in[2], (const float*)d_in[4],
                          (const float*)d_in[6], (const float*)d_in[8]};
    const float* dw[4] = {(const float*)d_in[9],  (const float*)d_in[11],
                          (const float*)d_in[13], (const float*)d_in[15]};
    const float* db[4] = {(const float*)d_in[10], (const float*)d_in[12],
                          (const float*)d_in[14], (const float*)d_in[16]};
    const float* cb0 = (const float*)d_in[17];
    const float* cb1 = (const float*)d_in[18];
    const float* cb2 = (const float*)d_in[19];
    float* out = (float*)d_out;

    float *h0, *h1, *h2, *lat, *xq, *g0, *g1, *g2;
    cudaGetSymbolAddress((void**)&h0,  g_h0);
    cudaGetSymbolAddress((void**)&h1,  g_h1);
    cudaGetSymbolAddress((void**)&h2,  g_h2);
    cudaGetSymbolAddress((void**)&lat, g_lat);
    cudaGetSymbolAddress((void**)&xq,  g_xq);
    cudaGetSymbolAddress((void**)&g0,  g_g0);
    cudaGetSymbolAddress((void**)&g1,  g_g1);
    cudaGetSymbolAddress((void**)&g2,  g_g2);

    const size_t OFF_OUT  = 0;
    const size_t OFF_LOSS = (size_t)MROWS * 1024;
    const size_t OFF_IDX  = OFF_LOSS + 1;
    const size_t OFF_OH   = OFF_IDX + (size_t)MROWS * NQ;
    const size_t OFF_LG   = OFF_OH  + (size_t)MROWS * NQ * NE;

    const int SMEM_BYTES = SM_WORDS * 4;
    cudaFuncSetAttribute(gemm_hmma_kernel<true>,  cudaFuncAttributeMaxDynamicSharedMemorySize, SMEM_BYTES);
    cudaFuncSetAttribute(gemm_hmma_kernel<false>, cudaFuncAttributeMaxDynamicSharedMemorySize, SMEM_BYTES);

    const int MT = MROWS / 128;

    // encoder
    gemm_hmma_kernel<true ><<<dim3(8, MT), 256, SMEM_BYTES>>>(x,  ew[0], eb[0], h0,  512, 1024);
    gemm_hmma_kernel<true ><<<dim3(4, MT), 256, SMEM_BYTES>>>(h0, ew[1], eb[1], h1,  256, 512);
    gemm_hmma_kernel<true ><<<dim3(2, MT), 256, SMEM_BYTES>>>(h1, ew[2], eb[2], h2,  128, 256);
    gemm_nt_kernel<128, 32,16,8,4,false><<<dim3(1, MT), 128>>>(h2, ew[3], eb[3], lat, MROWS, 32, 128);

    // residual VQ
    zero_loss_kernel<<<1,1>>>();
    const size_t vq_smem = (size_t)(NQ*NE*CBPAD + NQ*NE + 2*ED + NE)*4 + (size_t)NE*4 + 4;
    cudaFuncSetAttribute(vq_kernel, cudaFuncAttributeMaxDynamicSharedMemorySize, (int)vq_smem);
    vq_kernel<<<MROWS/32, NE, vq_smem>>>(lat, cb0, cb1, cb2, xq,
                                         out + OFF_IDX, out + OFF_OH, out + OFF_LG, 32);
    finalize_kernel<<<1,1>>>(out + OFF_LOSS);

    // decoder
    gemm_hmma_kernel<true ><<<dim3(2,  MT), 256, SMEM_BYTES>>>(xq, dw[0], db[0], g0, 128,  32);
    gemm_hmma_kernel<true ><<<dim3(4,  MT), 256, SMEM_BYTES>>>(g0, dw[1], db[1], g1, 256, 128);
    gemm_hmma_kernel<true ><<<dim3(8,  MT), 256, SMEM_BYTES>>>(g1, dw[2], db[2], g2, 512, 256);
    gemm_hmma_kernel<false><<<dim3(16, MT), 256, SMEM_BYTES>>>(g2, dw[3], db[3], out + OFF_OUT, 1024, 512);
}

// round 7
// speedup vs baseline: 1.5260x; 1.5260x over previous
#include <cuda_runtime.h>
#include <cuda_fp16.h>
#include <cstdint>

#define MROWS 32768
#define NQ 3
#define NE 256
#define ED 32
#define CBPAD 33

#define LO_SCALE 4096.0f
#define LO_INV   (1.0f / 4096.0f)

// ---------------- scratch ----------------
__device__ float g_loss;
__device__ float g_h0[(size_t)MROWS * 512];
__device__ float g_h1[(size_t)MROWS * 256];
__device__ float g_h2[(size_t)MROWS * 128];
__device__ float g_lat[(size_t)MROWS * ED];
__device__ float g_xq [(size_t)MROWS * ED];
__device__ float g_g0[(size_t)MROWS * 128];
__device__ float g_g1[(size_t)MROWS * 256];
__device__ float g_g2[(size_t)MROWS * 512];

__device__ __forceinline__ void mma_f16(float* c,
    uint32_t a0, uint32_t a1, uint32_t a2, uint32_t a3, uint32_t b0, uint32_t b1) {
    asm volatile(
        "mma.sync.aligned.m16n8k16.row.col.f32.f16.f16.f32 "
        "{%0,%1,%2,%3}, {%4,%5,%6,%7}, {%8,%9}, {%0,%1,%2,%3};"
        : "+f"(c[0]), "+f"(c[1]), "+f"(c[2]), "+f"(c[3])
        : "r"(a0), "r"(a1), "r"(a2), "r"(a3), "r"(b0), "r"(b1));
}

// pack two fp32 -> (hi half2, lo half2 scaled by 2^12 to stay in normal range)
__device__ __forceinline__ void split_pack(float x0, float x1, uint32_t& hi, uint32_t& lo) {
    __half h0 = __float2half_rn(x0);
    __half h1 = __float2half_rn(x1);
    __half l0 = __float2half_rn((x0 - __half2float(h0)) * LO_SCALE);
    __half l1 = __float2half_rn((x1 - __half2float(h1)) * LO_SCALE);
    hi = (uint32_t)__half_as_ushort(h0) | ((uint32_t)__half_as_ushort(h1) << 16);
    lo = (uint32_t)__half_as_ushort(l0) | ((uint32_t)__half_as_ushort(l1) << 16);
}

// ---------------- HMMA fp16-split GEMM: C = relu?(A(MxK) @ W(NxK)^T + bias) ----------------
// CTA tile 128(M) x 64(N) x 32(K). 256 threads, 8 warps (4M x 2N), warp tile 32x32.
// acc1 accumulates hi*hi; acc2 accumulates hi*lo' + lo'*hi (lo' = lo * 2^12).
// Final: C = acc1 + acc2 * 2^-12 + bias.
#define HPITCH 20
#define SM_A_HI 0
#define SM_A_LO (128 * HPITCH)
#define SM_B_HI (256 * HPITCH)
#define SM_B_LO (320 * HPITCH)
#define SM_WORDS (384 * HPITCH)

template<bool RELU>
__global__ void __launch_bounds__(256, 2)
gemm_hmma_kernel(const float* __restrict__ A, const float* __restrict__ W,
                 const float* __restrict__ bias, float* __restrict__ C,
                 int N, int K)
{
    extern __shared__ uint32_t sm[];

    const int tid = threadIdx.x;
    const int bn = blockIdx.x * 64;
    const int bm = blockIdx.y * 128;
    const int w = tid >> 5, lane = tid & 31;
    const int wm = (w & 3) * 32;
    const int wn = (w >> 2) * 32;
    const int qr = lane >> 2;
    const int qc = lane & 3;

    float acc1[2][4][4], acc2[2][4][4];
    #pragma unroll
    for (int i = 0; i < 2; i++)
        #pragma unroll
        for (int j = 0; j < 4; j++)
            #pragma unroll
            for (int k = 0; k < 4; k++) { acc1[i][j][k] = 0.f; acc2[i][j][k] = 0.f; }

    const int nk = K >> 5;
    const int k4 = K >> 2;

    for (int ck = 0; ck < nk; ck++) {
        // ---- stage gmem -> fp16 split -> smem ----
        const float4* Ag = (const float4*)A + (size_t)bm * k4 + ck * 8;
        const float4* Wg = (const float4*)W + (size_t)bn * k4 + ck * 8;
        if (ck > 0) __syncthreads();
        #pragma unroll
        for (int i = 0; i < 4; i++) {               // A: 1024 float4
            int idx = tid + i * 256;
            int r = idx >> 3, c4 = idx & 7;
            float4 v = Ag[(size_t)r * k4 + c4];
            uint32_t h0, l0, h1, l1;
            split_pack(v.x, v.y, h0, l0);
            split_pack(v.z, v.w, h1, l1);
            const int base = r * HPITCH + c4 * 2;
            sm[SM_A_HI + base]     = h0;
            sm[SM_A_HI + base + 1] = h1;
            sm[SM_A_LO + base]     = l0;
            sm[SM_A_LO + base + 1] = l1;
        }
        #pragma unroll
        for (int i = 0; i < 2; i++) {               // B: 512 float4
            int idx = tid + i * 256;
            int r = idx >> 3, c4 = idx & 7;
            float4 v = Wg[(size_t)r * k4 + c4];
            uint32_t h0, l0, h1, l1;
            split_pack(v.x, v.y, h0, l0);
            split_pack(v.z, v.w, h1, l1);
            const int base = r * HPITCH + c4 * 2;
            sm[SM_B_HI + base]     = h0;
            sm[SM_B_HI + base + 1] = h1;
            sm[SM_B_LO + base]     = l0;
            sm[SM_B_LO + base + 1] = l1;
        }
        __syncthreads();

        // ---- compute: 2 k-steps of 16 ----
        uint32_t ax[2][2][4];   // [mt][ks][frag]  (A hi, then reused for A lo)
        #pragma unroll
        for (int mt = 0; mt < 2; mt++)
            #pragma unroll
            for (int ks = 0; ks < 2; ks++) {
                const int r0 = SM_A_HI + (wm + mt * 16 + qr) * HPITCH + ks * 8 + qc;
                ax[mt][ks][0] = sm[r0];
                ax[mt][ks][1] = sm[r0 + 8 * HPITCH];
                ax[mt][ks][2] = sm[r0 + 4];
                ax[mt][ks][3] = sm[r0 + 8 * HPITCH + 4];
            }
        // pass 1: hi*hi -> acc1 ; pass 2: hi*lo' -> acc2
        #pragma unroll
        for (int nt = 0; nt < 4; nt++) {
            const int rb = (wn + nt * 8 + qr) * HPITCH + qc;
            uint32_t bh[2][2], bl[2][2];
            #pragma unroll
            for (int ks = 0; ks < 2; ks++) {
                bh[ks][0] = sm[SM_B_HI + rb + ks * 8];
                bh[ks][1] = sm[SM_B_HI + rb + ks * 8 + 4];
            }
            #pragma unroll
            for (int ks = 0; ks < 2; ks++)
                #pragma unroll
                for (int mt = 0; mt < 2; mt++)
                    mma_f16(acc1[mt][nt], ax[mt][ks][0], ax[mt][ks][1],
                            ax[mt][ks][2], ax[mt][ks][3], bh[ks][0], bh[ks][1]);
            #pragma unroll
            for (int ks = 0; ks < 2; ks++) {
                bl[ks][0] = sm[SM_B_LO + rb + ks * 8];
                bl[ks][1] = sm[SM_B_LO + rb + ks * 8 + 4];
            }
            #pragma unroll
            for (int ks = 0; ks < 2; ks++)
                #pragma unroll
                for (int mt = 0; mt < 2; mt++)
                    mma_f16(acc2[mt][nt], ax[mt][ks][0], ax[mt][ks][1],
                            ax[mt][ks][2], ax[mt][ks][3], bl[ks][0], bl[ks][1]);
        }
        // pass 3: lo'*hi -> acc2
        #pragma unroll
        for (int mt = 0; mt < 2; mt++)
            #pragma unroll
            for (int ks = 0; ks < 2; ks++) {
                const int r0 = SM_A_LO + (wm + mt * 16 + qr) * HPITCH + ks * 8 + qc;
                ax[mt][ks][0] = sm[r0];
                ax[mt][ks][1] = sm[r0 + 8 * HPITCH];
                ax[mt][ks][2] = sm[r0 + 4];
                ax[mt][ks][3] = sm[r0 + 8 * HPITCH + 4];
            }
        #pragma unroll
        for (int nt = 0; nt < 4; nt++) {
            const int rb = (wn + nt * 8 + qr) * HPITCH + qc;
            uint32_t bh[2][2];
            #pragma unroll
            for (int ks = 0; ks < 2; ks++) {
                bh[ks][0] = sm[SM_B_HI + rb + ks * 8];
                bh[ks][1] = sm[SM_B_HI + rb + ks * 8 + 4];
            }
            #pragma unroll
            for (int ks = 0; ks < 2; ks++)
                #pragma unroll
                for (int mt = 0; mt < 2; mt++)
                    mma_f16(acc2[mt][nt], ax[mt][ks][0], ax[mt][ks][1],
                            ax[mt][ks][2], ax[mt][ks][3], bh[ks][0], bh[ks][1]);
        }
    }

    // ---- epilogue: combine accumulators, bias + relu, float2 stores ----
    #pragma unroll
    for (int nt = 0; nt < 4; nt++) {
        const int col = bn + wn + nt * 8 + qc * 2;
        const float b0 = bias[col], b1 = bias[col + 1];
        #pragma unroll
        for (int mt = 0; mt < 2; mt++) {
            const int row = bm + wm + mt * 16 + qr;
            float2 v0, v1;
            v0.x = fmaf(acc2[mt][nt][0], LO_INV, acc1[mt][nt][0]) + b0;
            v0.y = fmaf(acc2[mt][nt][1], LO_INV, acc1[mt][nt][1]) + b1;
            v1.x = fmaf(acc2[mt][nt][2], LO_INV, acc1[mt][nt][2]) + b0;
            v1.y = fmaf(acc2[mt][nt][3], LO_INV, acc1[mt][nt][3]) + b1;
            if (RELU) {
                v0.x = fmaxf(v0.x, 0.f); v0.y = fmaxf(v0.y, 0.f);
                v1.x = fmaxf(v1.x, 0.f); v1.y = fmaxf(v1.y, 0.f);
            }
            *(float2*)(C + (size_t)row * N + col) = v0;
            *(float2*)(C + (size_t)(row + 8) * N + col) = v1;
        }
    }
}

// ---------------- SIMT fp32 GEMM (N=32 latent layer) ----------------
template<int BM, int BN, int BK, int TM, int TN, bool RELU>
__global__ void __launch_bounds__((BM/TM)*(BN/TN))
gemm_nt_kernel(const float* __restrict__ A, const float* __restrict__ W,
               const float* __restrict__ bias, float* __restrict__ C,
               int M, int N, int K)
{
    constexpr int THREADS = (BM/TM)*(BN/TN);
    __shared__ float As[BK][BM];
    __shared__ float Ws[BK][BN];

    const int bm = blockIdx.y * BM;
    const int bn = blockIdx.x * BN;
    const int tid = threadIdx.x;
    const int tn = (tid % (BN/TN)) * TN;
    const int tm = (tid / (BN/TN)) * TM;

    float acc[TM][TN];
    #pragma unroll
    for (int i = 0; i < TM; i++)
        #pragma unroll
        for (int j = 0; j < TN; j++) acc[i][j] = 0.f;

    for (int k0 = 0; k0 < K; k0 += BK) {
        constexpr int A_LOADS = (BM*BK) / (4*THREADS);
        #pragma unroll
        for (int i = 0; i < A_LOADS; i++) {
            int idx = (tid + i*THREADS) * 4;
            int r = idx / BK, c = idx % BK;
            float4 v = *(const float4*)(A + (size_t)(bm + r)*K + k0 + c);
            As[c+0][r] = v.x; As[c+1][r] = v.y; As[c+2][r] = v.z; As[c+3][r] = v.w;
        }
        constexpr int W_LOADS = (BN*BK) / (4*THREADS);
        #pragma unroll
        for (int i = 0; i < W_LOADS; i++) {
            int idx = (tid + i*THREADS) * 4;
            int r = idx / BK, c = idx % BK;
            float4 v = *(const float4*)(W + (size_t)(bn + r)*K + k0 + c);
            Ws[c+0][r] = v.x; Ws[c+1][r] = v.y; Ws[c+2][r] = v.z; Ws[c+3][r] = v.w;
        }
        __syncthreads();

        #pragma unroll
        for (int k = 0; k < BK; k++) {
            float ar[TM], wr[TN];
            #pragma unroll
            for (int i = 0; i < TM; i += 4) {
                float4 v = *(const float4*)(&As[k][tm + i]);
                ar[i+0] = v.x; ar[i+1] = v.y; ar[i+2] = v.z; ar[i+3] = v.w;
            }
            #pragma unroll
            for (int j = 0; j < TN; j += 4) {
                float4 v = *(const float4*)(&Ws[k][tn + j]);
                wr[j+0] = v.x; wr[j+1] = v.y; wr[j+2] = v.z; wr[j+3] = v.w;
            }
            #pragma unroll
            for (int i = 0; i < TM; i++)
                #pragma unroll
                for (int j = 0; j < TN; j++)
                    acc[i][j] = fmaf(ar[i], wr[j], acc[i][j]);
        }
        __syncthreads();
    }

    #pragma unroll
    for (int i = 0; i < TM; i++)
        #pragma unroll
        for (int j = 0; j < TN; j++) {
            float v = acc[i][j] + bias[bn + tn + j];
            if (RELU) v = fmaxf(v, 0.f);
            C[(size_t)(bm + tm + i)*N + bn + tn + j] = v;
        }
}

// ---------------- fused residual-VQ kernel ----------------
__global__ void __launch_bounds__(NE)
vq_kernel(const float* __restrict__ latent,
          const float* __restrict__ cb0, const float* __restrict__ cb1,
          const float* __restrict__ cb2,
          float* __restrict__ xq,
          float* __restrict__ out_idx, float* __restrict__ out_oh,
          float* __restrict__ out_logits,
          int rows_per_block)
{
    extern __shared__ float smf[];
    float* cbs   = smf;
    float* cnorm = cbs + NQ*NE*CBPAD;
    float* resid = cnorm + NQ*NE;
    float* xqrow = resid + ED;
    float* red_v = xqrow + ED;
    int*   red_i = (int*)(red_v + NE);
    float* s_rn  = (float*)(red_i + NE);

    const int t = threadIdx.x;

    const float* srcs[NQ] = {cb0, cb1, cb2};
    for (int q = 0; q < NQ; q++)
        for (int i = t; i < NE*ED; i += NE) {
            int r = i / ED, c = i % ED;
            cbs[(q*NE + r)*CBPAD + c] = srcs[q][i];
        }
    __syncthreads();
    for (int q = 0; q < NQ; q++) {
        const float* row = &cbs[(q*NE + t)*CBPAD];
        float s = 0.f;
        #pragma unroll
        for (int k = 0; k < ED; k++) s = fmaf(row[k], row[k], s);
        cnorm[q*NE + t] = s;
    }
    __syncthreads();

    float loss_acc = 0.f;
    const int row0 = blockIdx.x * rows_per_block;
    const int row1 = min(row0 + rows_per_block, MROWS);

    for (int r = row0; r < row1; r++) {
        if (t < ED) { resid[t] = latent[(size_t)r*ED + t]; xqrow[t] = 0.f; }
        __syncthreads();

        for (int q = 0; q < NQ; q++) {
            if (t < 32) {
                float v = resid[t]; v = v*v;
                #pragma unroll
                for (int o = 16; o; o >>= 1) v += __shfl_xor_sync(0xffffffffu, v, o);
                if (t == 0) s_rn[0] = v;
            }
            __syncthreads();
            const float rnorm = s_rn[0];

            const float* crow = &cbs[(q*NE + t)*CBPAD];
            float dot = 0.f;
            #pragma unroll
            for (int k = 0; k < ED; k++) dot = fmaf(resid[k], crow[k], dot);
            float d = rnorm + cnorm[q*NE + t] - 2.f*dot;
            out_logits[((size_t)r*NQ + q)*NE + t] = d;

            red_v[t] = d; red_i[t] = t;
            __syncthreads();
            #pragma unroll
            for (int s = NE/2; s > 0; s >>= 1) {
                if (t < s) {
                    float v2 = red_v[t+s]; int i2 = red_i[t+s];
                    if (v2 < red_v[t] || (v2 == red_v[t] && i2 < red_i[t])) {
                        red_v[t] = v2; red_i[t] = i2;
                    }
                }
                __syncthreads();
            }
            const int best = red_i[0];

            out_oh[((size_t)r*NQ + q)*NE + t] = (t == best) ? 1.f : 0.f;
            if (t == 0) out_idx[(size_t)r*NQ + q] = (float)best;

            if (t < 32) {
                float c  = cbs[(q*NE + best)*CBPAD + t];
                float rv = resid[t];
                float diff = c - rv;
                float xres = rv + diff;
                float sq = diff*diff;
                #pragma unroll
                for (int o = 16; o; o >>= 1) sq += __shfl_xor_sync(0xffffffffu, sq, o);
                if (t == 0) loss_acc += sq;
                resid[t] = rv - xres;
                xqrow[t] += xres;
            }
            __syncthreads();
        }
        if (t < ED) xq[(size_t)r*ED + t] = xqrow[t];
        __syncthreads();
    }
    if (t == 0) atomicAdd(&g_loss, loss_acc);
}

__global__ void zero_loss_kernel() { g_loss = 0.f; }

__global__ void finalize_kernel(float* __restrict__ loss_out)
{
    loss_out[0] = g_loss * (1.25f / (3.0f * (float)MROWS * (float)ED));
}

// ---------------- launch ----------------
extern "C" void kernel_launch(void* const* d_in, const int* in_sizes, int n_in,
                              void* d_out, int out_size)
{
    const float* x   = (const float*)d_in[0];
    const float* ew[4] = {(const float*)d_in[1], (const float*)d_in[3],
                          (const float*)d_in[5], (const float*)d_in[7]};
    const float* eb[4] = {(const float*)d_in[2], (const float*)d_in[4],
                          (const float*)d_in[6], (const float*)d_in[8]};
    const float* dw[4] = {(const float*)d_in[9],  (const float*)d_in[11],
                          (const float*)d_in[13], (const float*)d_in[15]};
    const float* db[4] = {(const float*)d_in[10], (const float*)d_in[12],
                          (const float*)d_in[14], (const float*)d_in[16]};
    const float* cb0 = (const float*)d_in[17];
    const float* cb1 = (const float*)d_in[18];
    const float* cb2 = (const float*)d_in[19];
    float* out = (float*)d_out;

    float *h0, *h1, *h2, *lat, *xq, *g0, *g1, *g2;
    cudaGetSymbolAddress((void**)&h0,  g_h0);
    cudaGetSymbolAddress((void**)&h1,  g_h1);
    cudaGetSymbolAddress((void**)&h2,  g_h2);
    cudaGetSymbolAddress((void**)&lat, g_lat);
    cudaGetSymbolAddress((void**)&xq,  g_xq);
    cudaGetSymbolAddress((void**)&g0,  g_g0);
    cudaGetSymbolAddress((void**)&g1,  g_g1);
    cudaGetSymbolAddress((void**)&g2,  g_g2);

    const size_t OFF_OUT  = 0;
    const size_t OFF_LOSS = (size_t)MROWS * 1024;
    const size_t OFF_IDX  = OFF_LOSS + 1;
    const size_t OFF_OH   = OFF_IDX + (size_t)MROWS * NQ;
    const size_t OFF_LG   = OFF_OH  + (size_t)MROWS * NQ * NE;

    const int SMEM_BYTES = SM_WORDS * 4;
    cudaFuncSetAttribute(gemm_hmma_kernel<true>,  cudaFuncAttributeMaxDynamicSharedMemorySize, SMEM_BYTES);
    cudaFuncSetAttribute(gemm_hmma_kernel<false>, cudaFuncAttributeMaxDynamicSharedMemorySize, SMEM_BYTES);

    const int MT = MROWS / 128;

    // encoder
    gemm_hmma_kernel<true ><<<dim3(8, MT), 256, SMEM_BYTES>>>(x,  ew[0], eb[0], h0,  512, 1024);
    gemm_hmma_kernel<true ><<<dim3(4, MT), 256, SMEM_BYTES>>>(h0, ew[1], eb[1], h1,  256, 512);
    gemm_hmma_kernel<true ><<<dim3(2, MT), 256, SMEM_BYTES>>>(h1, ew[2], eb[2], h2,  128, 256);
    gemm_nt_kernel<128, 32,16,8,4,false><<<dim3(1, MT), 128>>>(h2, ew[3], eb[3], lat, MROWS, 32, 128);

    // residual VQ
    zero_loss_kernel<<<1,1>>>();
    const size_t vq_smem = (size_t)(NQ*NE*CBPAD + NQ*NE + 2*ED + NE)*4 + (size_t)NE*4 + 4;
    cudaFuncSetAttribute(vq_kernel, cudaFuncAttributeMaxDynamicSharedMemorySize, (int)vq_smem);
    vq_kernel<<<MROWS/32, NE, vq_smem>>>(lat, cb0, cb1, cb2, xq,
                                         out + OFF_IDX, out + OFF_OH, out + OFF_LG, 32);
    finalize_kernel<<<1,1>>>(out + OFF_LOSS);

    // decoder
    gemm_hmma_kernel<true ><<<dim3(2,  MT), 256, SMEM_BYTES>>>(xq, dw[0], db[0], g0, 128,  32);
    gemm_hmma_kernel<true ><<<dim3(4,  MT), 256, SMEM_BYTES>>>(g0, dw[1], db[1], g1, 256, 128);
    gemm_hmma_kernel<true ><<<dim3(8,  MT), 256, SMEM_BYTES>>>(g1, dw[2], db[2], g2, 512, 256);
    gemm_hmma_kernel<false><<<dim3(16, MT), 256, SMEM_BYTES>>>(g2, dw[3], db[3], out + OFF_OUT, 1024, 512);
}